// round 3
// baseline (speedup 1.0000x reference)
#include <cuda_runtime.h>
#include <cuda_bf16.h>
#include <math.h>

// Problem constants
#define BB 16
#define TT 1024
#define CC 256
#define HH 4
#define KK 31
#define PADK 15
#define BT (BB * TT)          // 16384 tokens
#define C2 (2 * CC)           // 512
#define NSMALL (KK + HH * KK) // 31 + 124 = 155
#define NSP 160               // padded to multiple of 4 (alignment for float4)
#define NWW (HH * KK)         // 124

// -------------------- device scratch (no allocations allowed) ---------------
__device__ float g_h[(size_t)BT * C2];        // GLU pre-activation 16384x512
__device__ float g_x[(size_t)BT * CC];        // x (post-GLU)       16384x256
__device__ float g_raw[(size_t)BT * NSP];     // [wfk | logits | pad] 16384x160
__device__ float g_attn[(size_t)BT * NWW];    // softmax probs      16384x124
__device__ float g_z[(size_t)BT * C2];        // [y | xf]           16384x512
__device__ float g_wsmall[(size_t)CC * NSP];
__device__ float g_bsmall[NSP];

// -------------------- generic tiled fp32 GEMM: C = A@W + bias --------------
// A: MxK row-major, W: KxN row-major, C: MxN (ldc). M%64==0, K%16==0, N%4==0.
#define GBM 64
#define GBN 64
#define GBK 16

__global__ __launch_bounds__(256, 2) void sgemm_bias(
    const float* __restrict__ A, const float* __restrict__ W,
    const float* __restrict__ bias, float* __restrict__ Cm,
    int M, int N, int Kd, int ldc)
{
    __shared__ float As[GBK][GBM];
    __shared__ float Ws[GBK][GBN];
    const int tid = threadIdx.x;
    const int m0 = blockIdx.y * GBM;
    const int n0 = blockIdx.x * GBN;
    const int tx = tid & 15;   // 0..15 -> n micro
    const int ty = tid >> 4;   // 0..15 -> m micro

    const int a_m = tid >> 2;          // 0..63
    const int a_k = (tid & 3) * 4;     // 0,4,8,12
    const int w_k = tid >> 4;          // 0..15
    const int w_n = (tid & 15) * 4;    // 0..60

    float acc[4][4];
#pragma unroll
    for (int i = 0; i < 4; i++)
#pragma unroll
        for (int j = 0; j < 4; j++) acc[i][j] = 0.f;

    for (int k0 = 0; k0 < Kd; k0 += GBK) {
        // load A tile (M%64==0, K%16==0 -> always aligned & in-range)
        float4 av = *reinterpret_cast<const float4*>(
            &A[(size_t)(m0 + a_m) * Kd + k0 + a_k]);
        As[a_k + 0][a_m] = av.x;
        As[a_k + 1][a_m] = av.y;
        As[a_k + 2][a_m] = av.z;
        As[a_k + 3][a_m] = av.w;
        // load W tile; N%4==0 so any in-range float4 is aligned
        float4 wv;
        int nbase = n0 + w_n;
        if (nbase + 3 < N) {
            wv = *reinterpret_cast<const float4*>(
                &W[(size_t)(k0 + w_k) * N + nbase]);
        } else {
            wv.x = wv.y = wv.z = wv.w = 0.f;
        }
        *reinterpret_cast<float4*>(&Ws[w_k][w_n]) = wv;
        __syncthreads();
#pragma unroll
        for (int kk = 0; kk < GBK; kk++) {
            float4 a4 = *reinterpret_cast<const float4*>(&As[kk][ty * 4]);
            float4 b4 = *reinterpret_cast<const float4*>(&Ws[kk][tx * 4]);
            float ar[4] = {a4.x, a4.y, a4.z, a4.w};
            float br[4] = {b4.x, b4.y, b4.z, b4.w};
#pragma unroll
            for (int i = 0; i < 4; i++)
#pragma unroll
                for (int j = 0; j < 4; j++) acc[i][j] = fmaf(ar[i], br[j], acc[i][j]);
        }
        __syncthreads();
    }
#pragma unroll
    for (int i = 0; i < 4; i++) {
        size_t row = (size_t)(m0 + ty * 4 + i) * ldc;
#pragma unroll
        for (int j = 0; j < 4; j++) {
            int n = n0 + tx * 4 + j;
            if (n < N) Cm[row + n] = acc[i][j] + bias[n];
        }
    }
}

// -------------------- GLU: x = a * sigmoid(g) -------------------------------
__global__ __launch_bounds__(256) void glu_kernel(const float* __restrict__ h,
                                                  float* __restrict__ x)
{
    size_t i = (size_t)blockIdx.x * 256 + threadIdx.x; // over BT*CC
    size_t t = i >> 8;
    int c = (int)(i & 255);
    float a = h[t * C2 + c];
    float g = h[t * C2 + CC + c];
    x[i] = a * (1.f / (1.f + expf(-g)));
}

// -------------------- pack [wf | ww | 0pad] and [bf | bw | 0pad] ------------
__global__ __launch_bounds__(256) void pack_small(
    const float* __restrict__ wf, const float* __restrict__ ww,
    const float* __restrict__ bf, const float* __restrict__ bw,
    float* __restrict__ Wc, float* __restrict__ bc)
{
    int i = blockIdx.x * 256 + threadIdx.x;
    if (i < CC * NSP) {
        int k = i / NSP, n = i % NSP;
        float v = 0.f;
        if (n < KK) v = wf[k * KK + n];
        else if (n < NSMALL) v = ww[k * NWW + (n - KK)];
        Wc[i] = v;
    }
    if (i < NSP) {
        float v = 0.f;
        if (i < KK) v = bf[i];
        else if (i < NSMALL) v = bw[i - KK];
        bc[i] = v;
    }
}

// ---------- per-token: channel conv xf + banded softmax (one warp/token) ----
__global__ __launch_bounds__(256) void post_small(
    const float* __restrict__ raw, const float* __restrict__ x,
    const int* __restrict__ mask, float* __restrict__ attn,
    float* __restrict__ z)
{
    __shared__ float xpad[8][CC + 2 * PADK]; // 8 warps x 286
    const int warp = threadIdx.x >> 5;
    const int lane = threadIdx.x & 31;
    const int t = blockIdx.x * 8 + warp;  // grid=2048 -> exact
    const int b = t >> 10;
    const int tt = t & 1023;

    float* xp = xpad[warp];
    for (int i = lane; i < CC + 2 * PADK; i += 32) {
        int c = i - PADK;
        xp[i] = (c >= 0 && c < CC) ? x[(size_t)t * CC + c] : 0.f;
    }
    __syncwarp();

    const float mk = (mask[b * TT + tt] != 0) ? 1.f : 0.f;
    // channel conv: xf[c] = sum_j wfk[j] * x[c + j - PAD]
    float wv = (lane < KK) ? raw[(size_t)t * NSP + lane] : 0.f;
    float acc[8];
#pragma unroll
    for (int q = 0; q < 8; q++) acc[q] = 0.f;
    for (int j = 0; j < KK; j++) {
        float wj = __shfl_sync(0xffffffffu, wv, j);
#pragma unroll
        for (int q = 0; q < 8; q++) acc[q] = fmaf(wj, xp[lane + q * 32 + j], acc[q]);
    }
#pragma unroll
    for (int q = 0; q < 8; q++)
        z[(size_t)t * C2 + CC + lane + q * 32] = acc[q] * mk;

    // banded softmax per head over K=31 offsets (offset j -> s = tt + j - PAD)
    const int s = tt + lane - PADK;
    const bool valid = (lane < KK) && (s >= 0) && (s < TT);
#pragma unroll
    for (int h = 0; h < HH; h++) {
        float v = valid ? raw[(size_t)t * NSP + KK + h * KK + lane] : -INFINITY;
        float mx = v;
#pragma unroll
        for (int o = 16; o; o >>= 1) mx = fmaxf(mx, __shfl_xor_sync(0xffffffffu, mx, o));
        float e = valid ? expf(v - mx) : 0.f;
        float sm = e;
#pragma unroll
        for (int o = 16; o; o >>= 1) sm += __shfl_xor_sync(0xffffffffu, sm, o);
        if (lane < KK) attn[(size_t)t * NWW + h * KK + lane] = e / sm;
    }
}

// ---------- banded attention apply: y[t,c] = sum_j p[t,h,j]*x[t+j-PAD,c] ----
#define TCTILE 64
#define TCROWS (TCTILE + 2 * PADK) // 94
__global__ __launch_bounds__(256) void timeconv(
    const float* __restrict__ x, const float* __restrict__ attn,
    const int* __restrict__ mask, float* __restrict__ z)
{
    extern __shared__ float smem[];
    float* xs = smem;                        // TCROWS * CC
    float* ats = smem + TCROWS * CC;         // TCTILE * NWW
    __shared__ float msk[TCTILE];

    const int b = blockIdx.x >> 4;           // T/TCTILE = 16 tiles per batch
    const int tb = (blockIdx.x & 15) * TCTILE;
    const int tid = threadIdx.x;
    const int c = tid;                       // 0..255

    for (int r = 0; r < TCROWS; r++) {
        int s = tb - PADK + r;
        xs[r * CC + c] = (s >= 0 && s < TT)
            ? x[((size_t)b * TT + s) * CC + c] : 0.f;
    }
    for (int i = tid; i < TCTILE * NWW; i += 256)
        ats[i] = attn[((size_t)b * TT + tb) * NWW + i];
    if (tid < TCTILE) msk[tid] = (mask[b * TT + tb + tid] != 0) ? 1.f : 0.f;
    __syncthreads();

    const int h = c >> 6;
    for (int tt = 0; tt < TCTILE; tt++) {
        const float* a = &ats[tt * NWW + h * KK];
        const float* xr = &xs[tt * CC + c];
        float acc = 0.f;
#pragma unroll
        for (int j = 0; j < KK; j++) acc = fmaf(a[j], xr[j * CC], acc);
        z[((size_t)b * TT + tb + tt) * C2 + c] = acc * msk[tt];
    }
}

// ---------------------------------------------------------------------------
extern "C" void kernel_launch(void* const* d_in, const int* in_sizes, int n_in,
                              void* d_out, int out_size)
{
    const float* query = (const float*)d_in[0];
    // d_in[1] = key, d_in[2] = value  (unused by the reference math)
    const int* mask = (const int*)d_in[3];
    const float* w1 = (const float*)d_in[4];
    const float* b1 = (const float*)d_in[5];
    const float* w2 = (const float*)d_in[6];
    const float* b2 = (const float*)d_in[7];
    const float* ww = (const float*)d_in[8];
    const float* bw = (const float*)d_in[9];
    const float* wf = (const float*)d_in[10];
    const float* bf = (const float*)d_in[11];
    float* out = (float*)d_out;

    void* p;
    cudaGetSymbolAddress(&p, g_h);      float* dh = (float*)p;
    cudaGetSymbolAddress(&p, g_x);      float* dx = (float*)p;
    cudaGetSymbolAddress(&p, g_raw);    float* draw = (float*)p;
    cudaGetSymbolAddress(&p, g_attn);   float* dattn = (float*)p;
    cudaGetSymbolAddress(&p, g_z);      float* dz = (float*)p;
    cudaGetSymbolAddress(&p, g_wsmall); float* dws = (float*)p;
    cudaGetSymbolAddress(&p, g_bsmall); float* dbs = (float*)p;

    static bool attr_done = false;
    if (!attr_done) {
        cudaFuncSetAttribute(timeconv, cudaFuncAttributeMaxDynamicSharedMemorySize,
                             (TCROWS * CC + TCTILE * NWW) * (int)sizeof(float));
        attr_done = true;
    }

    // 1) h = query @ w1 + b1   (16384x512)
    sgemm_bias<<<dim3(C2 / GBN, BT / GBM), 256>>>(query, w1, b1, dh, BT, C2, CC, C2);
    // 2) x = GLU(h)
    glu_kernel<<<(BT * CC) / 256, 256>>>(dh, dx);
    // 3) pack small weights (padded to 160), then raw = x @ Wc + bc
    pack_small<<<(CC * NSP + 255) / 256, 256>>>(wf, ww, bf, bw, dws, dbs);
    sgemm_bias<<<dim3((NSP + GBN - 1) / GBN, BT / GBM), 256>>>(
        dx, dws, dbs, draw, BT, NSP, CC, NSP);
    // 4) channel conv xf (-> z[:,256:512]) + banded softmax (-> attn)
    post_small<<<BT / 8, 256>>>(draw, dx, mask, dattn, dz);
    // 5) banded attention apply (-> z[:,0:256])
    timeconv<<<BB * (TT / TCTILE), 256,
               (TCROWS * CC + TCTILE * NWW) * sizeof(float)>>>(dx, dattn, mask, dz);
    // 6) out = z @ w2 + b2
    sgemm_bias<<<dim3(CC / GBN, BT / GBM), 256>>>(dz, w2, b2, out, BT, CC, C2, CC);
}

// round 6
// speedup vs baseline: 1.3587x; 1.3587x over previous
#include <cuda_runtime.h>
#include <cuda_bf16.h>
#include <math.h>
#include <stdint.h>

// Problem constants
#define BB 16
#define TT 1024
#define CC 256
#define HH 4
#define KK 31
#define PADK 15
#define BT (BB * TT)          // 16384 tokens
#define C2 (2 * CC)           // 512
#define NSMALL (KK + HH * KK) // 155
#define NSP 160               // padded row stride for raw
#define NWW (HH * KK)         // 124
#define NSMPAD 256            // padded N rows for small weight (>=192 needed)

// -------------------- device scratch ---------------------------------------
__device__ float g_h[(size_t)BT * C2];
__device__ float g_x[(size_t)BT * CC];
__device__ __nv_bfloat16 g_qhi[(size_t)BT * CC];
__device__ __nv_bfloat16 g_qlo[(size_t)BT * CC];
__device__ __nv_bfloat16 g_xhi[(size_t)BT * CC];
__device__ __nv_bfloat16 g_xlo[(size_t)BT * CC];
__device__ __nv_bfloat16 g_zhi[(size_t)BT * C2];
__device__ __nv_bfloat16 g_zlo[(size_t)BT * C2];
__device__ float g_raw[(size_t)BT * NSP];
__device__ float g_attn[(size_t)BT * NWW];
__device__ __nv_bfloat16 g_w1t_hi[(size_t)C2 * CC];
__device__ __nv_bfloat16 g_w1t_lo[(size_t)C2 * CC];
__device__ __nv_bfloat16 g_w2t_hi[(size_t)CC * C2];
__device__ __nv_bfloat16 g_w2t_lo[(size_t)CC * C2];
__device__ __nv_bfloat16 g_wst_hi[(size_t)NSMPAD * CC];
__device__ __nv_bfloat16 g_wst_lo[(size_t)NSMPAD * CC];
__device__ float g_bsmall[NSP];

static __device__ __forceinline__ void split2(float v, __nv_bfloat16& h, __nv_bfloat16& l) {
    h = __float2bfloat16(v);
    l = __float2bfloat16(v - __bfloat162float(h));
}

__device__ __forceinline__ void mma16816(float* c, uint32_t a0, uint32_t a1,
                                         uint32_t a2, uint32_t a3,
                                         uint32_t b0, uint32_t b1) {
    asm volatile(
        "mma.sync.aligned.m16n8k16.row.col.f32.bf16.bf16.f32 "
        "{%0,%1,%2,%3}, {%4,%5,%6,%7}, {%8,%9}, {%0,%1,%2,%3};"
        : "+f"(c[0]), "+f"(c[1]), "+f"(c[2]), "+f"(c[3])
        : "r"(a0), "r"(a1), "r"(a2), "r"(a3), "r"(b0), "r"(b1));
}

// ---------------- split-bf16 GEMM via mma.sync: C = A@B^T + bias ------------
// A hi/lo: M x Kt bf16 row-major (K contiguous). B hi/lo: Nrows x Kt bf16
// row-major (= W^T, K contiguous). D = Ahi*Bhi + Ahi*Blo + Alo*Bhi (fp32 acc).
// Block tile 128(M) x 64(N), BK=32, 8 warps (warp tile 32x32).
#define BMT 128
#define BNT 64
#define BKT 32
#define APAD 40   // bf16 stride for smem tiles (conflict-free fragment loads)

__global__ __launch_bounds__(256) void gemm_split_mma(
    const __nv_bfloat16* __restrict__ Ahi, const __nv_bfloat16* __restrict__ Alo,
    const __nv_bfloat16* __restrict__ Bhi, const __nv_bfloat16* __restrict__ Blo,
    const float* __restrict__ bias, float* __restrict__ Cm,
    int Kt, int ldc, int Nout)
{
    __shared__ __nv_bfloat16 Ahs[BMT][APAD];
    __shared__ __nv_bfloat16 Bhs[BNT][APAD];

    const int tid = threadIdx.x;
    const int wid = tid >> 5;
    const int lane = tid & 31;
    const int m0 = blockIdx.y * BMT;
    const int n0 = blockIdx.x * BNT;
    const int wm = (wid & 3) * 32;   // warp M offset in tile
    const int wn = (wid >> 2) * 32;  // warp N offset in tile

    float acc[2][4][4];
#pragma unroll
    for (int i = 0; i < 2; i++)
#pragma unroll
        for (int j = 0; j < 4; j++)
#pragma unroll
            for (int q = 0; q < 4; q++) acc[i][j][q] = 0.f;

    const __nv_bfloat16* APh[3] = { Ahi, Ahi, Alo };
    const __nv_bfloat16* BPh[3] = { Bhi, Blo, Bhi };

    // global load indices
    const int a_row0 = tid >> 2;          // +64 for second
    const int a_c16 = (tid & 3) * 8;      // element col
    const int b_row = tid >> 2;
    const int b_c16 = (tid & 3) * 8;

    const int r8 = lane >> 2;             // 0..7
    const int cp = (lane & 3) * 2;        // 0,2,4,6

    for (int p = 0; p < 3; p++) {
        const __nv_bfloat16* Ap = APh[p];
        const __nv_bfloat16* Bp = BPh[p];
        for (int k0 = 0; k0 < Kt; k0 += BKT) {
            __syncthreads();
            // load A tile 128x32 (2 uint4/thread) and B tile 64x32 (1/thread)
            *reinterpret_cast<uint4*>(&Ahs[a_row0][a_c16]) =
                *reinterpret_cast<const uint4*>(Ap + (size_t)(m0 + a_row0) * Kt + k0 + a_c16);
            *reinterpret_cast<uint4*>(&Ahs[a_row0 + 64][a_c16]) =
                *reinterpret_cast<const uint4*>(Ap + (size_t)(m0 + a_row0 + 64) * Kt + k0 + a_c16);
            *reinterpret_cast<uint4*>(&Bhs[b_row][b_c16]) =
                *reinterpret_cast<const uint4*>(Bp + (size_t)(n0 + b_row) * Kt + k0 + b_c16);
            __syncthreads();

#pragma unroll
            for (int ks = 0; ks < 2; ks++) {
                const int kb = ks * 16;
                // A fragments for 2 m16 tiles
                uint32_t af[2][4];
#pragma unroll
                for (int im = 0; im < 2; im++) {
                    const int rb = wm + im * 16;
                    af[im][0] = *reinterpret_cast<const uint32_t*>(&Ahs[rb + r8][kb + cp]);
                    af[im][1] = *reinterpret_cast<const uint32_t*>(&Ahs[rb + r8 + 8][kb + cp]);
                    af[im][2] = *reinterpret_cast<const uint32_t*>(&Ahs[rb + r8][kb + cp + 8]);
                    af[im][3] = *reinterpret_cast<const uint32_t*>(&Ahs[rb + r8 + 8][kb + cp + 8]);
                }
                // B fragments for 4 n8 tiles
                uint32_t bf[4][2];
#pragma unroll
                for (int jn = 0; jn < 4; jn++) {
                    const int nb = wn + jn * 8;
                    bf[jn][0] = *reinterpret_cast<const uint32_t*>(&Bhs[nb + r8][kb + cp]);
                    bf[jn][1] = *reinterpret_cast<const uint32_t*>(&Bhs[nb + r8][kb + cp + 8]);
                }
#pragma unroll
                for (int im = 0; im < 2; im++)
#pragma unroll
                    for (int jn = 0; jn < 4; jn++)
                        mma16816(acc[im][jn], af[im][0], af[im][1], af[im][2], af[im][3],
                                 bf[jn][0], bf[jn][1]);
            }
        }
    }

    // epilogue: c0,c1 at (row = r8, col = cp), c2,c3 at (row = r8+8, col = cp)
#pragma unroll
    for (int im = 0; im < 2; im++) {
#pragma unroll
        for (int jn = 0; jn < 4; jn++) {
            const int col = n0 + wn + jn * 8 + cp;
            if (col < Nout) {
                const float bx = bias[col], by = bias[col + 1];
                const int row0 = m0 + wm + im * 16 + r8;
                float2 v0 = { acc[im][jn][0] + bx, acc[im][jn][1] + by };
                float2 v1 = { acc[im][jn][2] + bx, acc[im][jn][3] + by };
                *reinterpret_cast<float2*>(&Cm[(size_t)row0 * ldc + col]) = v0;
                *reinterpret_cast<float2*>(&Cm[(size_t)(row0 + 8) * ldc + col]) = v1;
            }
        }
    }
}

// -------------------- prep kernels ------------------------------------------
__global__ __launch_bounds__(256) void split_act(const float* __restrict__ src,
                                                 __nv_bfloat16* __restrict__ hi,
                                                 __nv_bfloat16* __restrict__ lo,
                                                 int n)
{
    int i = blockIdx.x * 256 + threadIdx.x;
    if (i < n) split2(src[i], hi[i], lo[i]);
}

__global__ __launch_bounds__(256) void wtrans_split(
    const float* __restrict__ W, __nv_bfloat16* __restrict__ hi,
    __nv_bfloat16* __restrict__ lo, int Kd, int N)
{
    int i = blockIdx.x * 256 + threadIdx.x;
    if (i >= N * Kd) return;
    int n = i / Kd, k = i % Kd;
    split2(W[(size_t)k * N + n], hi[i], lo[i]);
}

__global__ __launch_bounds__(256) void wsmall_prep(
    const float* __restrict__ wf, const float* __restrict__ ww,
    const float* __restrict__ bf, const float* __restrict__ bw,
    __nv_bfloat16* __restrict__ hi, __nv_bfloat16* __restrict__ lo,
    float* __restrict__ bc)
{
    int i = blockIdx.x * 256 + threadIdx.x;
    if (i < NSMPAD * CC) {
        int n = i / CC, k = i % CC;
        float v = 0.f;
        if (n < KK) v = wf[k * KK + n];
        else if (n < NSMALL) v = ww[k * NWW + (n - KK)];
        split2(v, hi[i], lo[i]);
    }
    if (i < NSP) {
        float v = 0.f;
        if (i < KK) v = bf[i];
        else if (i < NSMALL) v = bw[i - KK];
        bc[i] = v;
    }
}

__global__ __launch_bounds__(256) void glu_split(const float* __restrict__ h,
                                                 float* __restrict__ x,
                                                 __nv_bfloat16* __restrict__ xhi,
                                                 __nv_bfloat16* __restrict__ xlo)
{
    size_t i = (size_t)blockIdx.x * 256 + threadIdx.x;
    size_t t = i >> 8;
    int c = (int)(i & 255);
    float a = h[t * C2 + c];
    float g = h[t * C2 + CC + c];
    float v = a * (1.f / (1.f + expf(-g)));
    x[i] = v;
    split2(v, xhi[i], xlo[i]);
}

// ---------- per-token: channel conv xf + banded softmax (one warp/token) ----
__global__ __launch_bounds__(256) void post_small(
    const float* __restrict__ raw, const float* __restrict__ x,
    const int* __restrict__ mask, float* __restrict__ attn,
    __nv_bfloat16* __restrict__ zhi, __nv_bfloat16* __restrict__ zlo)
{
    __shared__ float xpad[8][CC + 2 * PADK];
    const int warp = threadIdx.x >> 5;
    const int lane = threadIdx.x & 31;
    const int t = blockIdx.x * 8 + warp;
    const int b = t >> 10;
    const int tt = t & 1023;

    float* xp = xpad[warp];
    for (int i = lane; i < CC + 2 * PADK; i += 32) {
        int c = i - PADK;
        xp[i] = (c >= 0 && c < CC) ? x[(size_t)t * CC + c] : 0.f;
    }
    __syncwarp();

    const float mk = (mask[b * TT + tt] != 0) ? 1.f : 0.f;
    float wv = (lane < KK) ? raw[(size_t)t * NSP + lane] : 0.f;
    float acc[8];
#pragma unroll
    for (int q = 0; q < 8; q++) acc[q] = 0.f;
    for (int j = 0; j < KK; j++) {
        float wj = __shfl_sync(0xffffffffu, wv, j);
#pragma unroll
        for (int q = 0; q < 8; q++) acc[q] = fmaf(wj, xp[lane + q * 32 + j], acc[q]);
    }
#pragma unroll
    for (int q = 0; q < 8; q++) {
        float v = acc[q] * mk;
        __nv_bfloat16 h_, l_;
        split2(v, h_, l_);
        size_t o = (size_t)t * C2 + CC + lane + q * 32;
        zhi[o] = h_; zlo[o] = l_;
    }

    const int s = tt + lane - PADK;
    const bool valid = (lane < KK) && (s >= 0) && (s < TT);
#pragma unroll
    for (int h = 0; h < HH; h++) {
        float v = valid ? raw[(size_t)t * NSP + KK + h * KK + lane] : -INFINITY;
        float mx = v;
#pragma unroll
        for (int o = 16; o; o >>= 1) mx = fmaxf(mx, __shfl_xor_sync(0xffffffffu, mx, o));
        float e = valid ? expf(v - mx) : 0.f;
        float sm = e;
#pragma unroll
        for (int o = 16; o; o >>= 1) sm += __shfl_xor_sync(0xffffffffu, sm, o);
        if (lane < KK) attn[(size_t)t * NWW + h * KK + lane] = e / sm;
    }
}

// ---------- banded attention apply ------------------------------------------
#define TCTILE 64
#define TCROWS (TCTILE + 2 * PADK) // 94
__global__ __launch_bounds__(256) void timeconv(
    const float* __restrict__ x, const float* __restrict__ attn,
    const int* __restrict__ mask,
    __nv_bfloat16* __restrict__ zhi, __nv_bfloat16* __restrict__ zlo)
{
    extern __shared__ float smem[];
    float* xs = smem;                        // TCROWS * CC
    float* ats = smem + TCROWS * CC;         // TCTILE * NWW
    __shared__ float msk[TCTILE];

    const int b = blockIdx.x >> 4;
    const int tb = (blockIdx.x & 15) * TCTILE;
    const int tid = threadIdx.x;
    const int c = tid;

    for (int r = 0; r < TCROWS; r++) {
        int s = tb - PADK + r;
        xs[r * CC + c] = (s >= 0 && s < TT)
            ? x[((size_t)b * TT + s) * CC + c] : 0.f;
    }
    for (int i = tid; i < TCTILE * NWW; i += 256)
        ats[i] = attn[((size_t)b * TT + tb) * NWW + i];
    if (tid < TCTILE) msk[tid] = (mask[b * TT + tb + tid] != 0) ? 1.f : 0.f;
    __syncthreads();

    const int h = c >> 6;
    for (int tt = 0; tt < TCTILE; tt++) {
        const float* a = &ats[tt * NWW + h * KK];
        const float* xr = &xs[tt * CC + c];
        float acc = 0.f;
#pragma unroll
        for (int j = 0; j < KK; j++) acc = fmaf(a[j], xr[j * CC], acc);
        float v = acc * msk[tt];
        __nv_bfloat16 h_, l_;
        split2(v, h_, l_);
        size_t o = ((size_t)b * TT + tb + tt) * C2 + c;
        zhi[o] = h_; zlo[o] = l_;
    }
}

// ---------------------------------------------------------------------------
extern "C" void kernel_launch(void* const* d_in, const int* in_sizes, int n_in,
                              void* d_out, int out_size)
{
    const float* query = (const float*)d_in[0];
    const int* mask = (const int*)d_in[3];
    const float* w1 = (const float*)d_in[4];
    const float* b1 = (const float*)d_in[5];
    const float* w2 = (const float*)d_in[6];
    const float* b2 = (const float*)d_in[7];
    const float* ww = (const float*)d_in[8];
    const float* bw = (const float*)d_in[9];
    const float* wf = (const float*)d_in[10];
    const float* bf = (const float*)d_in[11];
    float* out = (float*)d_out;

    void* p;
    cudaGetSymbolAddress(&p, g_h);      float* dh = (float*)p;
    cudaGetSymbolAddress(&p, g_x);      float* dx = (float*)p;
    cudaGetSymbolAddress(&p, g_qhi);    __nv_bfloat16* dqhi = (__nv_bfloat16*)p;
    cudaGetSymbolAddress(&p, g_qlo);    __nv_bfloat16* dqlo = (__nv_bfloat16*)p;
    cudaGetSymbolAddress(&p, g_xhi);    __nv_bfloat16* dxhi = (__nv_bfloat16*)p;
    cudaGetSymbolAddress(&p, g_xlo);    __nv_bfloat16* dxlo = (__nv_bfloat16*)p;
    cudaGetSymbolAddress(&p, g_zhi);    __nv_bfloat16* dzhi = (__nv_bfloat16*)p;
    cudaGetSymbolAddress(&p, g_zlo);    __nv_bfloat16* dzlo = (__nv_bfloat16*)p;
    cudaGetSymbolAddress(&p, g_raw);    float* draw = (float*)p;
    cudaGetSymbolAddress(&p, g_attn);   float* dattn = (float*)p;
    cudaGetSymbolAddress(&p, g_w1t_hi); __nv_bfloat16* w1h = (__nv_bfloat16*)p;
    cudaGetSymbolAddress(&p, g_w1t_lo); __nv_bfloat16* w1l = (__nv_bfloat16*)p;
    cudaGetSymbolAddress(&p, g_w2t_hi); __nv_bfloat16* w2h = (__nv_bfloat16*)p;
    cudaGetSymbolAddress(&p, g_w2t_lo); __nv_bfloat16* w2l = (__nv_bfloat16*)p;
    cudaGetSymbolAddress(&p, g_wst_hi); __nv_bfloat16* wsh = (__nv_bfloat16*)p;
    cudaGetSymbolAddress(&p, g_wst_lo); __nv_bfloat16* wsl = (__nv_bfloat16*)p;
    cudaGetSymbolAddress(&p, g_bsmall); float* dbs = (float*)p;

    static bool attr_done = false;
    if (!attr_done) {
        cudaFuncSetAttribute(timeconv, cudaFuncAttributeMaxDynamicSharedMemorySize,
                             (TCROWS * CC + TCTILE * NWW) * (int)sizeof(float));
        attr_done = true;
    }

    // prep: operand splits
    split_act<<<(BT * CC) / 256, 256>>>(query, dqhi, dqlo, BT * CC);
    wtrans_split<<<(C2 * CC + 255) / 256, 256>>>(w1, w1h, w1l, CC, C2);
    wtrans_split<<<(CC * C2 + 255) / 256, 256>>>(w2, w2h, w2l, C2, CC);
    wsmall_prep<<<(NSMPAD * CC + 255) / 256, 256>>>(wf, ww, bf, bw, wsh, wsl, dbs);

    // 1) h = query @ w1 + b1   (16384x512, K=256)
    gemm_split_mma<<<dim3(C2 / BNT, BT / BMT), 256>>>(
        dqhi, dqlo, w1h, w1l, b1, dh, CC, C2, C2);
    // 2) x = GLU(h) (+ split)
    glu_split<<<(BT * CC) / 256, 256>>>(dh, dx, dxhi, dxlo);
    // 3) raw = x @ [wf|ww] + [bf|bw]  (16384x160, K=256; 3 N-blocks cover 192)
    gemm_split_mma<<<dim3((NSP + BNT - 1) / BNT, BT / BMT), 256>>>(
        dxhi, dxlo, wsh, wsl, dbs, draw, CC, NSP, NSP);
    // 4) channel conv xf (-> z[:,256:512]) + banded softmax (-> attn)
    post_small<<<BT / 8, 256>>>(draw, dx, mask, dattn, dzhi, dzlo);
    // 5) banded attention apply (-> z[:,0:256])
    timeconv<<<BB * (TT / TCTILE), 256,
               (TCROWS * CC + TCTILE * NWW) * sizeof(float)>>>(dx, dattn, mask, dzhi, dzlo);
    // 6) out = z @ w2 + b2   (16384x256, K=512)
    gemm_split_mma<<<dim3(CC / BNT, BT / BMT), 256>>>(
        dzhi, dzlo, w2h, w2l, b2, out, C2, CC, CC);
}

// round 8
// speedup vs baseline: 1.5776x; 1.1611x over previous
#include <cuda_runtime.h>
#include <cuda_bf16.h>
#include <math.h>
#include <stdint.h>

// Problem constants
#define BB 16
#define TT 1024
#define CC 256
#define HH 4
#define KK 31
#define PADK 15
#define BT (BB * TT)          // 16384 tokens
#define C2 (2 * CC)           // 512
#define NSMALL (KK + HH * KK) // 155
#define NSP 160               // padded row stride for raw
#define NWW (HH * KK)         // 124
#define NSMPAD 256            // padded N rows for small weight

// -------------------- device scratch ---------------------------------------
__device__ float g_h[(size_t)BT * C2];
__device__ float g_x[(size_t)BT * CC];
__device__ __nv_bfloat16 g_qhi[(size_t)BT * CC];
__device__ __nv_bfloat16 g_qlo[(size_t)BT * CC];
__device__ __nv_bfloat16 g_xhi[(size_t)BT * CC];
__device__ __nv_bfloat16 g_xlo[(size_t)BT * CC];
__device__ __nv_bfloat16 g_zhi[(size_t)BT * C2];
__device__ __nv_bfloat16 g_zlo[(size_t)BT * C2];
__device__ float g_raw[(size_t)BT * NSP];
__device__ float g_attn[(size_t)BT * NWW];
__device__ __nv_bfloat16 g_w1t_hi[(size_t)C2 * CC];
__device__ __nv_bfloat16 g_w1t_lo[(size_t)C2 * CC];
__device__ __nv_bfloat16 g_w2t_hi[(size_t)CC * C2];
__device__ __nv_bfloat16 g_w2t_lo[(size_t)CC * C2];
__device__ __nv_bfloat16 g_wst_hi[(size_t)NSMPAD * CC];
__device__ __nv_bfloat16 g_wst_lo[(size_t)NSMPAD * CC];
__device__ float g_bsmall[NSP];

static __device__ __forceinline__ void split2(float v, __nv_bfloat16& h, __nv_bfloat16& l) {
    h = __float2bfloat16(v);
    l = __float2bfloat16(v - __bfloat162float(h));
}

__device__ __forceinline__ void mma16816(float* c, uint32_t a0, uint32_t a1,
                                         uint32_t a2, uint32_t a3,
                                         uint32_t b0, uint32_t b1) {
    asm volatile(
        "mma.sync.aligned.m16n8k16.row.col.f32.bf16.bf16.f32 "
        "{%0,%1,%2,%3}, {%4,%5,%6,%7}, {%8,%9}, {%0,%1,%2,%3};"
        : "+f"(c[0]), "+f"(c[1]), "+f"(c[2]), "+f"(c[3])
        : "r"(a0), "r"(a1), "r"(a2), "r"(a3), "r"(b0), "r"(b1));
}

__device__ __forceinline__ uint32_t smem_u32(const void* p) {
    uint32_t a;
    asm("{ .reg .u64 t; cvta.to.shared.u64 t, %1; cvt.u32.u64 %0, t; }"
        : "=r"(a) : "l"(p));
    return a;
}
__device__ __forceinline__ void cpa16(uint32_t saddr, const void* g) {
    asm volatile("cp.async.cg.shared.global [%0], [%1], 16;" :: "r"(saddr), "l"(g));
}
#define CP_COMMIT() asm volatile("cp.async.commit_group;" ::: "memory")
#define CP_WAIT0()  asm volatile("cp.async.wait_group 0;" ::: "memory")

// ---------------- fused split-bf16 GEMM (cp.async double-buffered) ----------
// C = (Ahi+Alo) @ (Bhi+Blo)^T + bias, dropping lo*lo.
// A hi/lo: M x Kt bf16 row-major. B hi/lo: Nrows x Kt bf16 row-major (W^T).
// Block tile 128x128, BK=32, 8 warps (2 M x 4 N), warp tile 64x32.
#define BMT 128
#define BNT 128
#define BKT 32
#define APAD 40   // bf16 elems per smem row (80B = 5*16B: cp.async-aligned, conflict-free)
#define TILE_ELEMS (128 * APAD)
#define STAGE_ELEMS (4 * TILE_ELEMS)
#define GSMEM_BYTES (2 * STAGE_ELEMS * 2)   // 81920

__global__ __launch_bounds__(256) void gemm_split_mma(
    const __nv_bfloat16* __restrict__ Ahi, const __nv_bfloat16* __restrict__ Alo,
    const __nv_bfloat16* __restrict__ Bhi, const __nv_bfloat16* __restrict__ Blo,
    const float* __restrict__ bias, float* __restrict__ Cm,
    int Kt, int ldc, int Nout)
{
    extern __shared__ __align__(16) __nv_bfloat16 sm[];
    const int tid = threadIdx.x;
    const int wid = tid >> 5;
    const int lane = tid & 31;
    const int m0 = blockIdx.y * BMT;
    const int n0 = blockIdx.x * BNT;
    const int wm = (wid & 1) * 64;
    const int wn = (wid >> 1) * 32;
    const int r8 = lane >> 2;
    const int cp = (lane & 3) * 2;

    const __nv_bfloat16* srcs[4] = { Ahi, Alo, Bhi, Blo };
    const int bases[4] = { m0, m0, n0, n0 };

    // per-thread load coords: 2 chunks per tile
    const int c0 = tid, c1 = tid + 256;         // chunk ids in [0,512)
    const int lr0 = c0 >> 2, lc0 = (c0 & 3) * 8;
    const int lr1 = c1 >> 2, lc1 = (c1 & 3) * 8;
    const uint32_t smbase = smem_u32(sm);

    float acc[4][4][4];
#pragma unroll
    for (int i = 0; i < 4; i++)
#pragma unroll
        for (int j = 0; j < 4; j++)
#pragma unroll
            for (int q = 0; q < 4; q++) acc[i][j][q] = 0.f;

    const int NK = Kt >> 5;   // BKT=32

    // pipeline prologue: stage 0
#pragma unroll
    for (int t = 0; t < 4; t++) {
        const __nv_bfloat16* sp = srcs[t];
        cpa16(smbase + (uint32_t)((t * 128 + lr0) * APAD + lc0) * 2,
              sp + (size_t)(bases[t] + lr0) * Kt + lc0);
        cpa16(smbase + (uint32_t)((t * 128 + lr1) * APAD + lc1) * 2,
              sp + (size_t)(bases[t] + lr1) * Kt + lc1);
    }
    CP_COMMIT();
    CP_WAIT0();
    __syncthreads();

    for (int kc = 0; kc < NK; kc++) {
        if (kc + 1 < NK) {
            const int sb = ((kc + 1) & 1) * STAGE_ELEMS;
            const int k0 = (kc + 1) << 5;
#pragma unroll
            for (int t = 0; t < 4; t++) {
                const __nv_bfloat16* sp = srcs[t];
                cpa16(smbase + (uint32_t)(sb + (t * 128 + lr0) * APAD + lc0) * 2,
                      sp + (size_t)(bases[t] + lr0) * Kt + k0 + lc0);
                cpa16(smbase + (uint32_t)(sb + (t * 128 + lr1) * APAD + lc1) * 2,
                      sp + (size_t)(bases[t] + lr1) * Kt + k0 + lc1);
            }
            CP_COMMIT();
        }
        // compute on buffer kc&1
        const __nv_bfloat16* Ah_ = sm + (kc & 1) * STAGE_ELEMS;
        const __nv_bfloat16* Al_ = Ah_ + TILE_ELEMS;
        const __nv_bfloat16* Bh_ = Ah_ + 2 * TILE_ELEMS;
        const __nv_bfloat16* Bl_ = Ah_ + 3 * TILE_ELEMS;
#pragma unroll
        for (int ks = 0; ks < 2; ks++) {
            const int kb = ks * 16;
            uint32_t afh[4][4], afl[4][4];
#pragma unroll
            for (int im = 0; im < 4; im++) {
                const int rb = wm + im * 16;
                afh[im][0] = *reinterpret_cast<const uint32_t*>(&Ah_[(rb + r8) * APAD + kb + cp]);
                afh[im][1] = *reinterpret_cast<const uint32_t*>(&Ah_[(rb + r8 + 8) * APAD + kb + cp]);
                afh[im][2] = *reinterpret_cast<const uint32_t*>(&Ah_[(rb + r8) * APAD + kb + cp + 8]);
                afh[im][3] = *reinterpret_cast<const uint32_t*>(&Ah_[(rb + r8 + 8) * APAD + kb + cp + 8]);
            }
            uint32_t bfh[4][2], bfl[4][2];
#pragma unroll
            for (int jn = 0; jn < 4; jn++) {
                const int nb = wn + jn * 8;
                bfh[jn][0] = *reinterpret_cast<const uint32_t*>(&Bh_[(nb + r8) * APAD + kb + cp]);
                bfh[jn][1] = *reinterpret_cast<const uint32_t*>(&Bh_[(nb + r8) * APAD + kb + cp + 8]);
                bfl[jn][0] = *reinterpret_cast<const uint32_t*>(&Bl_[(nb + r8) * APAD + kb + cp]);
                bfl[jn][1] = *reinterpret_cast<const uint32_t*>(&Bl_[(nb + r8) * APAD + kb + cp + 8]);
            }
            // combo hh + hl
#pragma unroll
            for (int im = 0; im < 4; im++)
#pragma unroll
                for (int jn = 0; jn < 4; jn++) {
                    mma16816(acc[im][jn], afh[im][0], afh[im][1], afh[im][2], afh[im][3],
                             bfh[jn][0], bfh[jn][1]);
                    mma16816(acc[im][jn], afh[im][0], afh[im][1], afh[im][2], afh[im][3],
                             bfl[jn][0], bfl[jn][1]);
                }
            // combo lh
#pragma unroll
            for (int im = 0; im < 4; im++) {
                const int rb = wm + im * 16;
                afl[im][0] = *reinterpret_cast<const uint32_t*>(&Al_[(rb + r8) * APAD + kb + cp]);
                afl[im][1] = *reinterpret_cast<const uint32_t*>(&Al_[(rb + r8 + 8) * APAD + kb + cp]);
                afl[im][2] = *reinterpret_cast<const uint32_t*>(&Al_[(rb + r8) * APAD + kb + cp + 8]);
                afl[im][3] = *reinterpret_cast<const uint32_t*>(&Al_[(rb + r8 + 8) * APAD + kb + cp + 8]);
            }
#pragma unroll
            for (int im = 0; im < 4; im++)
#pragma unroll
                for (int jn = 0; jn < 4; jn++)
                    mma16816(acc[im][jn], afl[im][0], afl[im][1], afl[im][2], afl[im][3],
                             bfh[jn][0], bfh[jn][1]);
        }
        if (kc + 1 < NK) {
            CP_WAIT0();
            __syncthreads();
        }
    }

    // epilogue
#pragma unroll
    for (int im = 0; im < 4; im++) {
#pragma unroll
        for (int jn = 0; jn < 4; jn++) {
            const int col = n0 + wn + jn * 8 + cp;
            if (col < Nout) {
                const float bx = bias[col], by = bias[col + 1];
                const int row0 = m0 + wm + im * 16 + r8;
                float2 v0 = { acc[im][jn][0] + bx, acc[im][jn][1] + by };
                float2 v1 = { acc[im][jn][2] + bx, acc[im][jn][3] + by };
                *reinterpret_cast<float2*>(&Cm[(size_t)row0 * ldc + col]) = v0;
                *reinterpret_cast<float2*>(&Cm[(size_t)(row0 + 8) * ldc + col]) = v1;
            }
        }
    }
}

// -------------------- prep kernels ------------------------------------------
__global__ __launch_bounds__(256) void split_act(const float* __restrict__ src,
                                                 __nv_bfloat16* __restrict__ hi,
                                                 __nv_bfloat16* __restrict__ lo,
                                                 int n)
{
    int i = blockIdx.x * 256 + threadIdx.x;
    if (i < n) split2(src[i], hi[i], lo[i]);
}

__global__ __launch_bounds__(256) void wtrans_split(
    const float* __restrict__ W, __nv_bfloat16* __restrict__ hi,
    __nv_bfloat16* __restrict__ lo, int Kd, int N)
{
    int i = blockIdx.x * 256 + threadIdx.x;
    if (i >= N * Kd) return;
    int n = i / Kd, k = i % Kd;
    split2(W[(size_t)k * N + n], hi[i], lo[i]);
}

__global__ __launch_bounds__(256) void wsmall_prep(
    const float* __restrict__ wf, const float* __restrict__ ww,
    const float* __restrict__ bf, const float* __restrict__ bw,
    __nv_bfloat16* __restrict__ hi, __nv_bfloat16* __restrict__ lo,
    float* __restrict__ bc)
{
    int i = blockIdx.x * 256 + threadIdx.x;
    if (i < NSMPAD * CC) {
        int n = i / CC, k = i % CC;
        float v = 0.f;
        if (n < KK) v = wf[k * KK + n];
        else if (n < NSMALL) v = ww[k * NWW + (n - KK)];
        split2(v, hi[i], lo[i]);
    }
    if (i < NSP) {
        float v = 0.f;
        if (i < KK) v = bf[i];
        else if (i < NSMALL) v = bw[i - KK];
        bc[i] = v;
    }
}

__global__ __launch_bounds__(256) void glu_split(const float* __restrict__ h,
                                                 float* __restrict__ x,
                                                 __nv_bfloat16* __restrict__ xhi,
                                                 __nv_bfloat16* __restrict__ xlo)
{
    size_t i = (size_t)blockIdx.x * 256 + threadIdx.x;
    size_t t = i >> 8;
    int c = (int)(i & 255);
    float a = h[t * C2 + c];
    float g = h[t * C2 + CC + c];
    float v = a * (1.f / (1.f + expf(-g)));
    x[i] = v;
    split2(v, xhi[i], xlo[i]);
}

// ---------- per-token: channel conv xf + banded softmax (one warp/token) ----
__global__ __launch_bounds__(256) void post_small(
    const float* __restrict__ raw, const float* __restrict__ x,
    const int* __restrict__ mask, float* __restrict__ attn,
    __nv_bfloat16* __restrict__ zhi, __nv_bfloat16* __restrict__ zlo)
{
    __shared__ float xpad[8][CC + 2 * PADK];
    const int warp = threadIdx.x >> 5;
    const int lane = threadIdx.x & 31;
    const int t = blockIdx.x * 8 + warp;
    const int b = t >> 10;
    const int tt = t & 1023;

    float* xp = xpad[warp];
    for (int i = lane; i < CC + 2 * PADK; i += 32) {
        int c = i - PADK;
        xp[i] = (c >= 0 && c < CC) ? x[(size_t)t * CC + c] : 0.f;
    }
    __syncwarp();

    const float mk = (mask[b * TT + tt] != 0) ? 1.f : 0.f;
    float wv = (lane < KK) ? raw[(size_t)t * NSP + lane] : 0.f;
    float acc[8];
#pragma unroll
    for (int q = 0; q < 8; q++) acc[q] = 0.f;
    for (int j = 0; j < KK; j++) {
        float wj = __shfl_sync(0xffffffffu, wv, j);
#pragma unroll
        for (int q = 0; q < 8; q++) acc[q] = fmaf(wj, xp[lane + q * 32 + j], acc[q]);
    }
#pragma unroll
    for (int q = 0; q < 8; q++) {
        float v = acc[q] * mk;
        __nv_bfloat16 h_, l_;
        split2(v, h_, l_);
        size_t o = (size_t)t * C2 + CC + lane + q * 32;
        zhi[o] = h_; zlo[o] = l_;
    }

    const int s = tt + lane - PADK;
    const bool valid = (lane < KK) && (s >= 0) && (s < TT);
#pragma unroll
    for (int h = 0; h < HH; h++) {
        float v = valid ? raw[(size_t)t * NSP + KK + h * KK + lane] : -INFINITY;
        float mx = v;
#pragma unroll
        for (int o = 16; o; o >>= 1) mx = fmaxf(mx, __shfl_xor_sync(0xffffffffu, mx, o));
        float e = valid ? expf(v - mx) : 0.f;
        float sm = e;
#pragma unroll
        for (int o = 16; o; o >>= 1) sm += __shfl_xor_sync(0xffffffffu, sm, o);
        if (lane < KK) attn[(size_t)t * NWW + h * KK + lane] = e / sm;
    }
}

// ---------- banded attention apply ------------------------------------------
#define TCTILE 64
#define TCROWS (TCTILE + 2 * PADK) // 94
__global__ __launch_bounds__(256) void timeconv(
    const float* __restrict__ x, const float* __restrict__ attn,
    const int* __restrict__ mask,
    __nv_bfloat16* __restrict__ zhi, __nv_bfloat16* __restrict__ zlo)
{
    extern __shared__ float smemf[];
    float* xs = smemf;                       // TCROWS * CC
    float* ats = smemf + TCROWS * CC;        // TCTILE * NWW
    __shared__ float msk[TCTILE];

    const int b = blockIdx.x >> 4;
    const int tb = (blockIdx.x & 15) * TCTILE;
    const int tid = threadIdx.x;
    const int c = tid;

    for (int r = 0; r < TCROWS; r++) {
        int s = tb - PADK + r;
        xs[r * CC + c] = (s >= 0 && s < TT)
            ? x[((size_t)b * TT + s) * CC + c] : 0.f;
    }
    for (int i = tid; i < TCTILE * NWW; i += 256)
        ats[i] = attn[((size_t)b * TT + tb) * NWW + i];
    if (tid < TCTILE) msk[tid] = (mask[b * TT + tb + tid] != 0) ? 1.f : 0.f;
    __syncthreads();

    const int h = c >> 6;
    for (int tt = 0; tt < TCTILE; tt++) {
        const float* a = &ats[tt * NWW + h * KK];
        const float* xr = &xs[tt * CC + c];
        float acc = 0.f;
#pragma unroll
        for (int j = 0; j < KK; j++) acc = fmaf(a[j], xr[j * CC], acc);
        float v = acc * msk[tt];
        __nv_bfloat16 h_, l_;
        split2(v, h_, l_);
        size_t o = ((size_t)b * TT + tb + tt) * C2 + c;
        zhi[o] = h_; zlo[o] = l_;
    }
}

// ---------------------------------------------------------------------------
extern "C" void kernel_launch(void* const* d_in, const int* in_sizes, int n_in,
                              void* d_out, int out_size)
{
    const float* query = (const float*)d_in[0];
    const int* mask = (const int*)d_in[3];
    const float* w1 = (const float*)d_in[4];
    const float* b1 = (const float*)d_in[5];
    const float* w2 = (const float*)d_in[6];
    const float* b2 = (const float*)d_in[7];
    const float* ww = (const float*)d_in[8];
    const float* bw = (const float*)d_in[9];
    const float* wf = (const float*)d_in[10];
    const float* bf = (const float*)d_in[11];
    float* out = (float*)d_out;

    void* p;
    cudaGetSymbolAddress(&p, g_h);      float* dh = (float*)p;
    cudaGetSymbolAddress(&p, g_x);      float* dx = (float*)p;
    cudaGetSymbolAddress(&p, g_qhi);    __nv_bfloat16* dqhi = (__nv_bfloat16*)p;
    cudaGetSymbolAddress(&p, g_qlo);    __nv_bfloat16* dqlo = (__nv_bfloat16*)p;
    cudaGetSymbolAddress(&p, g_xhi);    __nv_bfloat16* dxhi = (__nv_bfloat16*)p;
    cudaGetSymbolAddress(&p, g_xlo);    __nv_bfloat16* dxlo = (__nv_bfloat16*)p;
    cudaGetSymbolAddress(&p, g_zhi);    __nv_bfloat16* dzhi = (__nv_bfloat16*)p;
    cudaGetSymbolAddress(&p, g_zlo);    __nv_bfloat16* dzlo = (__nv_bfloat16*)p;
    cudaGetSymbolAddress(&p, g_raw);    float* draw = (float*)p;
    cudaGetSymbolAddress(&p, g_attn);   float* dattn = (float*)p;
    cudaGetSymbolAddress(&p, g_w1t_hi); __nv_bfloat16* w1h = (__nv_bfloat16*)p;
    cudaGetSymbolAddress(&p, g_w1t_lo); __nv_bfloat16* w1l = (__nv_bfloat16*)p;
    cudaGetSymbolAddress(&p, g_w2t_hi); __nv_bfloat16* w2h = (__nv_bfloat16*)p;
    cudaGetSymbolAddress(&p, g_w2t_lo); __nv_bfloat16* w2l = (__nv_bfloat16*)p;
    cudaGetSymbolAddress(&p, g_wst_hi); __nv_bfloat16* wsh = (__nv_bfloat16*)p;
    cudaGetSymbolAddress(&p, g_wst_lo); __nv_bfloat16* wsl = (__nv_bfloat16*)p;
    cudaGetSymbolAddress(&p, g_bsmall); float* dbs = (float*)p;

    static bool attr_done = false;
    if (!attr_done) {
        cudaFuncSetAttribute(gemm_split_mma,
                             cudaFuncAttributeMaxDynamicSharedMemorySize, GSMEM_BYTES);
        cudaFuncSetAttribute(timeconv, cudaFuncAttributeMaxDynamicSharedMemorySize,
                             (TCROWS * CC + TCTILE * NWW) * (int)sizeof(float));
        attr_done = true;
    }

    // prep: operand splits
    split_act<<<(BT * CC) / 256, 256>>>(query, dqhi, dqlo, BT * CC);
    wtrans_split<<<(C2 * CC + 255) / 256, 256>>>(w1, w1h, w1l, CC, C2);
    wtrans_split<<<(CC * C2 + 255) / 256, 256>>>(w2, w2h, w2l, C2, CC);
    wsmall_prep<<<(NSMPAD * CC + 255) / 256, 256>>>(wf, ww, bf, bw, wsh, wsl, dbs);

    // 1) h = query @ w1 + b1   (16384x512, K=256)
    gemm_split_mma<<<dim3(C2 / BNT, BT / BMT), 256, GSMEM_BYTES>>>(
        dqhi, dqlo, w1h, w1l, b1, dh, CC, C2, C2);
    // 2) x = GLU(h) (+ split)
    glu_split<<<(BT * CC) / 256, 256>>>(dh, dx, dxhi, dxlo);
    // 3) raw = x @ [wf|ww] + [bf|bw]  (16384x160, K=256; 2 N-blocks of 128)
    gemm_split_mma<<<dim3(NSMPAD / BNT, BT / BMT), 256, GSMEM_BYTES>>>(
        dxhi, dxlo, wsh, wsl, dbs, draw, CC, NSP, NSP);
    // 4) channel conv xf (-> z[:,256:512]) + banded softmax (-> attn)
    post_small<<<BT / 8, 256>>>(draw, dx, mask, dattn, dzhi, dzlo);
    // 5) banded attention apply (-> z[:,0:256])
    timeconv<<<BB * (TT / TCTILE), 256,
               (TCROWS * CC + TCTILE * NWW) * sizeof(float)>>>(dx, dattn, mask, dzhi, dzlo);
    // 6) out = z @ w2 + b2   (16384x256, K=512)
    gemm_split_mma<<<dim3(CC / BNT, BT / BMT), 256, GSMEM_BYTES>>>(
        dzhi, dzlo, w2h, w2l, b2, out, C2, CC, CC);
}

// round 9
// speedup vs baseline: 1.7792x; 1.1278x over previous
#include <cuda_runtime.h>
#include <cuda_bf16.h>
#include <math.h>
#include <stdint.h>

// Problem constants
#define BB 16
#define TT 1024
#define CC 256
#define HH 4
#define KK 31
#define PADK 15
#define BT (BB * TT)          // 16384 tokens
#define C2 (2 * CC)           // 512
#define NSMALL (KK + HH * KK) // 155
#define NSP 160               // padded row stride for raw
#define NWW (HH * KK)         // 124
#define NSMPAD 256            // padded N rows for small weight

// -------------------- device scratch ---------------------------------------
__device__ float g_x[(size_t)BT * CC];
__device__ __nv_bfloat16 g_xhi[(size_t)BT * CC];
__device__ __nv_bfloat16 g_xlo[(size_t)BT * CC];
__device__ __nv_bfloat16 g_zhi[(size_t)BT * C2];
__device__ __nv_bfloat16 g_zlo[(size_t)BT * C2];
__device__ float g_raw[(size_t)BT * NSP];
__device__ float g_attn[(size_t)BT * NWW];
__device__ __nv_bfloat16 g_w1t_hi[(size_t)C2 * CC];
__device__ __nv_bfloat16 g_w1t_lo[(size_t)C2 * CC];
__device__ __nv_bfloat16 g_w2t_hi[(size_t)CC * C2];
__device__ __nv_bfloat16 g_w2t_lo[(size_t)CC * C2];
__device__ __nv_bfloat16 g_wst_hi[(size_t)NSMPAD * CC];
__device__ __nv_bfloat16 g_wst_lo[(size_t)NSMPAD * CC];
__device__ float g_bsmall[NSP];

static __device__ __forceinline__ void split2(float v, __nv_bfloat16& h, __nv_bfloat16& l) {
    h = __float2bfloat16(v);
    l = __float2bfloat16(v - __bfloat162float(h));
}

__device__ __forceinline__ void mma16816(float* c, uint32_t a0, uint32_t a1,
                                         uint32_t a2, uint32_t a3,
                                         uint32_t b0, uint32_t b1) {
    asm volatile(
        "mma.sync.aligned.m16n8k16.row.col.f32.bf16.bf16.f32 "
        "{%0,%1,%2,%3}, {%4,%5,%6,%7}, {%8,%9}, {%0,%1,%2,%3};"
        : "+f"(c[0]), "+f"(c[1]), "+f"(c[2]), "+f"(c[3])
        : "r"(a0), "r"(a1), "r"(a2), "r"(a3), "r"(b0), "r"(b1));
}

__device__ __forceinline__ uint32_t smem_u32(const void* p) {
    uint32_t a;
    asm("{ .reg .u64 t; cvta.to.shared.u64 t, %1; cvt.u32.u64 %0, t; }"
        : "=r"(a) : "l"(p));
    return a;
}
__device__ __forceinline__ void cpa16(uint32_t saddr, const void* g) {
    asm volatile("cp.async.cg.shared.global [%0], [%1], 16;" :: "r"(saddr), "l"(g));
}
#define CP_COMMIT() asm volatile("cp.async.commit_group;" ::: "memory")
#define CP_WAIT0()  asm volatile("cp.async.wait_group 0;" ::: "memory")

#define BMT 128
#define BNT 128
#define BKT 32
#define APAD 40   // bf16 elems per smem row
#define TILE_ELEMS (128 * APAD)

// ============ fused GEMM1 + GLU + split =====================================
// x = (q@w1+b1)[:, :256] * sigmoid((q@w1+b1)[:, 256:]) per 128-col slice.
// A = query fp32 (split in-flight). B = w1t hi/lo (512 x 256 bf16, K-major).
// grid (2, BT/128). Each CTA: twin 128x128 accumulators (a-half, g-half).
#define G1_STAGE (6 * TILE_ELEMS)
#define G1_SMEM_BYTES (2 * G1_STAGE * 2)   // 122880

__global__ __launch_bounds__(256) void gemm1_glu(
    const float* __restrict__ Q,
    const __nv_bfloat16* __restrict__ Wh, const __nv_bfloat16* __restrict__ Wl,
    const float* __restrict__ b1,
    float* __restrict__ X, __nv_bfloat16* __restrict__ Xhi,
    __nv_bfloat16* __restrict__ Xlo)
{
    extern __shared__ __align__(16) __nv_bfloat16 sm[];
    const int tid = threadIdx.x;
    const int wid = tid >> 5;
    const int lane = tid & 31;
    const int m0 = blockIdx.y * BMT;
    const int n0 = blockIdx.x * BNT;     // a-col base; g-cols at n0+256
    const int wm = (wid & 1) * 64;
    const int wn = (wid >> 1) * 32;
    const int r8 = lane >> 2;
    const int cp = (lane & 3) * 2;
    const uint32_t smbase = smem_u32(sm);

    // B sources (4 tiles): Ba_hi, Ba_lo, Bg_hi, Bg_lo -> smem tiles 2..5
    const __nv_bfloat16* bsrc[4] = { Wh, Wl, Wh, Wl };
    const int brow[4] = { n0, n0, n0 + 256, n0 + 256 };

    // chunk mapping: c in [0,512): row=c>>2, colc=c&3 (8 elems)
    const int c0 = tid, c1 = tid + 256;
    const int r0c = c0 >> 2, q0c = (c0 & 3) * 8;
    const int r1c = c1 >> 2, q1c = (c1 & 3) * 8;

    float acc_a[4][4][4], acc_g[4][4][4];
#pragma unroll
    for (int i = 0; i < 4; i++)
#pragma unroll
        for (int j = 0; j < 4; j++)
#pragma unroll
            for (int q = 0; q < 4; q++) { acc_a[i][j][q] = 0.f; acc_g[i][j][q] = 0.f; }

    const int NK = CC / BKT;  // 8
    float apre[2][8];

    // ---- prologue: stage 0
#pragma unroll
    for (int t = 0; t < 4; t++) {
        cpa16(smbase + (uint32_t)(((t + 2) * 128 + r0c) * APAD + q0c) * 2,
              bsrc[t] + (size_t)(brow[t] + r0c) * CC + q0c);
        cpa16(smbase + (uint32_t)(((t + 2) * 128 + r1c) * APAD + q1c) * 2,
              bsrc[t] + (size_t)(brow[t] + r1c) * CC + q1c);
    }
    CP_COMMIT();
    {
        *reinterpret_cast<float4*>(&apre[0][0]) = *reinterpret_cast<const float4*>(&Q[(size_t)(m0 + r0c) * CC + q0c]);
        *reinterpret_cast<float4*>(&apre[0][4]) = *reinterpret_cast<const float4*>(&Q[(size_t)(m0 + r0c) * CC + q0c + 4]);
        *reinterpret_cast<float4*>(&apre[1][0]) = *reinterpret_cast<const float4*>(&Q[(size_t)(m0 + r1c) * CC + q1c]);
        *reinterpret_cast<float4*>(&apre[1][4]) = *reinterpret_cast<const float4*>(&Q[(size_t)(m0 + r1c) * CC + q1c + 4]);
        __nv_bfloat16 h8[8], l8[8];
#pragma unroll
        for (int e = 0; e < 8; e++) split2(apre[0][e], h8[e], l8[e]);
        *reinterpret_cast<uint4*>(&sm[(0 * 128 + r0c) * APAD + q0c]) = *reinterpret_cast<uint4*>(h8);
        *reinterpret_cast<uint4*>(&sm[(1 * 128 + r0c) * APAD + q0c]) = *reinterpret_cast<uint4*>(l8);
#pragma unroll
        for (int e = 0; e < 8; e++) split2(apre[1][e], h8[e], l8[e]);
        *reinterpret_cast<uint4*>(&sm[(0 * 128 + r1c) * APAD + q1c]) = *reinterpret_cast<uint4*>(h8);
        *reinterpret_cast<uint4*>(&sm[(1 * 128 + r1c) * APAD + q1c]) = *reinterpret_cast<uint4*>(l8);
    }
    CP_WAIT0();
    __syncthreads();

    for (int kc = 0; kc < NK; kc++) {
        const int nxt = kc + 1;
        if (nxt < NK) {
            const int sb = (nxt & 1) * G1_STAGE;
            const int k0 = nxt << 5;
#pragma unroll
            for (int t = 0; t < 4; t++) {
                cpa16(smbase + (uint32_t)(sb + ((t + 2) * 128 + r0c) * APAD + q0c) * 2,
                      bsrc[t] + (size_t)(brow[t] + r0c) * CC + k0 + q0c);
                cpa16(smbase + (uint32_t)(sb + ((t + 2) * 128 + r1c) * APAD + q1c) * 2,
                      bsrc[t] + (size_t)(brow[t] + r1c) * CC + k0 + q1c);
            }
            CP_COMMIT();
            *reinterpret_cast<float4*>(&apre[0][0]) = *reinterpret_cast<const float4*>(&Q[(size_t)(m0 + r0c) * CC + k0 + q0c]);
            *reinterpret_cast<float4*>(&apre[0][4]) = *reinterpret_cast<const float4*>(&Q[(size_t)(m0 + r0c) * CC + k0 + q0c + 4]);
            *reinterpret_cast<float4*>(&apre[1][0]) = *reinterpret_cast<const float4*>(&Q[(size_t)(m0 + r1c) * CC + k0 + q1c]);
            *reinterpret_cast<float4*>(&apre[1][4]) = *reinterpret_cast<const float4*>(&Q[(size_t)(m0 + r1c) * CC + k0 + q1c + 4]);
        }

        // ---- compute stage kc
        const __nv_bfloat16* Ah_ = sm + (kc & 1) * G1_STAGE;
        const __nv_bfloat16* Al_ = Ah_ + TILE_ELEMS;
        const __nv_bfloat16* Bah = Ah_ + 2 * TILE_ELEMS;
        const __nv_bfloat16* Bal = Ah_ + 3 * TILE_ELEMS;
        const __nv_bfloat16* Bgh = Ah_ + 4 * TILE_ELEMS;
        const __nv_bfloat16* Bgl = Ah_ + 5 * TILE_ELEMS;
#pragma unroll
        for (int ks = 0; ks < 2; ks++) {
            const int kb = ks * 16;
            uint32_t afh[4][4], afl[4][4];
#pragma unroll
            for (int im = 0; im < 4; im++) {
                const int rb = wm + im * 16;
                afh[im][0] = *reinterpret_cast<const uint32_t*>(&Ah_[(rb + r8) * APAD + kb + cp]);
                afh[im][1] = *reinterpret_cast<const uint32_t*>(&Ah_[(rb + r8 + 8) * APAD + kb + cp]);
                afh[im][2] = *reinterpret_cast<const uint32_t*>(&Ah_[(rb + r8) * APAD + kb + cp + 8]);
                afh[im][3] = *reinterpret_cast<const uint32_t*>(&Ah_[(rb + r8 + 8) * APAD + kb + cp + 8]);
                afl[im][0] = *reinterpret_cast<const uint32_t*>(&Al_[(rb + r8) * APAD + kb + cp]);
                afl[im][1] = *reinterpret_cast<const uint32_t*>(&Al_[(rb + r8 + 8) * APAD + kb + cp]);
                afl[im][2] = *reinterpret_cast<const uint32_t*>(&Al_[(rb + r8) * APAD + kb + cp + 8]);
                afl[im][3] = *reinterpret_cast<const uint32_t*>(&Al_[(rb + r8 + 8) * APAD + kb + cp + 8]);
            }
            // a-half
            {
                uint32_t bh[4][2], bl[4][2];
#pragma unroll
                for (int jn = 0; jn < 4; jn++) {
                    const int nb = wn + jn * 8;
                    bh[jn][0] = *reinterpret_cast<const uint32_t*>(&Bah[(nb + r8) * APAD + kb + cp]);
                    bh[jn][1] = *reinterpret_cast<const uint32_t*>(&Bah[(nb + r8) * APAD + kb + cp + 8]);
                    bl[jn][0] = *reinterpret_cast<const uint32_t*>(&Bal[(nb + r8) * APAD + kb + cp]);
                    bl[jn][1] = *reinterpret_cast<const uint32_t*>(&Bal[(nb + r8) * APAD + kb + cp + 8]);
                }
#pragma unroll
                for (int im = 0; im < 4; im++)
#pragma unroll
                    for (int jn = 0; jn < 4; jn++) {
                        mma16816(acc_a[im][jn], afh[im][0], afh[im][1], afh[im][2], afh[im][3], bh[jn][0], bh[jn][1]);
                        mma16816(acc_a[im][jn], afh[im][0], afh[im][1], afh[im][2], afh[im][3], bl[jn][0], bl[jn][1]);
                        mma16816(acc_a[im][jn], afl[im][0], afl[im][1], afl[im][2], afl[im][3], bh[jn][0], bh[jn][1]);
                    }
            }
            // g-half
            {
                uint32_t bh[4][2], bl[4][2];
#pragma unroll
                for (int jn = 0; jn < 4; jn++) {
                    const int nb = wn + jn * 8;
                    bh[jn][0] = *reinterpret_cast<const uint32_t*>(&Bgh[(nb + r8) * APAD + kb + cp]);
                    bh[jn][1] = *reinterpret_cast<const uint32_t*>(&Bgh[(nb + r8) * APAD + kb + cp + 8]);
                    bl[jn][0] = *reinterpret_cast<const uint32_t*>(&Bgl[(nb + r8) * APAD + kb + cp]);
                    bl[jn][1] = *reinterpret_cast<const uint32_t*>(&Bgl[(nb + r8) * APAD + kb + cp + 8]);
                }
#pragma unroll
                for (int im = 0; im < 4; im++)
#pragma unroll
                    for (int jn = 0; jn < 4; jn++) {
                        mma16816(acc_g[im][jn], afh[im][0], afh[im][1], afh[im][2], afh[im][3], bh[jn][0], bh[jn][1]);
                        mma16816(acc_g[im][jn], afh[im][0], afh[im][1], afh[im][2], afh[im][3], bl[jn][0], bl[jn][1]);
                        mma16816(acc_g[im][jn], afl[im][0], afl[im][1], afl[im][2], afl[im][3], bh[jn][0], bh[jn][1]);
                    }
            }
        }

        if (nxt < NK) {
            const int sb = (nxt & 1) * G1_STAGE;
            __nv_bfloat16 h8[8], l8[8];
#pragma unroll
            for (int e = 0; e < 8; e++) split2(apre[0][e], h8[e], l8[e]);
            *reinterpret_cast<uint4*>(&sm[sb + (0 * 128 + r0c) * APAD + q0c]) = *reinterpret_cast<uint4*>(h8);
            *reinterpret_cast<uint4*>(&sm[sb + (1 * 128 + r0c) * APAD + q0c]) = *reinterpret_cast<uint4*>(l8);
#pragma unroll
            for (int e = 0; e < 8; e++) split2(apre[1][e], h8[e], l8[e]);
            *reinterpret_cast<uint4*>(&sm[sb + (0 * 128 + r1c) * APAD + q1c]) = *reinterpret_cast<uint4*>(h8);
            *reinterpret_cast<uint4*>(&sm[sb + (1 * 128 + r1c) * APAD + q1c]) = *reinterpret_cast<uint4*>(l8);
            CP_WAIT0();
            __syncthreads();
        }
    }

    // ---- epilogue: GLU + split ---------------------------------------------
#pragma unroll
    for (int im = 0; im < 4; im++) {
#pragma unroll
        for (int jn = 0; jn < 4; jn++) {
            const int lc = wn + jn * 8 + cp;
            const int col = n0 + lc;
            const float ba0 = b1[col], ba1 = b1[col + 1];
            const float bg0 = b1[col + 256], bg1 = b1[col + 257];
            const int row0 = m0 + wm + im * 16 + r8;
#pragma unroll
            for (int half = 0; half < 2; half++) {
                const int row = row0 + half * 8;
                float a0 = acc_a[im][jn][half * 2 + 0] + ba0;
                float a1 = acc_a[im][jn][half * 2 + 1] + ba1;
                float gg0 = acc_g[im][jn][half * 2 + 0] + bg0;
                float gg1 = acc_g[im][jn][half * 2 + 1] + bg1;
                float x0 = a0 * (1.f / (1.f + expf(-gg0)));
                float x1 = a1 * (1.f / (1.f + expf(-gg1)));
                size_t o = (size_t)row * CC + col;
                *reinterpret_cast<float2*>(&X[o]) = make_float2(x0, x1);
                __nv_bfloat16 h0, l0, h1, l1;
                split2(x0, h0, l0); split2(x1, h1, l1);
                __nv_bfloat162 ph; ph.x = h0; ph.y = h1;
                __nv_bfloat162 pl; pl.x = l0; pl.y = l1;
                *reinterpret_cast<__nv_bfloat162*>(&Xhi[o]) = ph;
                *reinterpret_cast<__nv_bfloat162*>(&Xlo[o]) = pl;
            }
        }
    }
}

// ---------------- generic fused split-bf16 GEMM (unchanged from R8) ---------
#define STAGE_ELEMS (4 * TILE_ELEMS)
#define GSMEM_BYTES (2 * STAGE_ELEMS * 2)   // 81920

__global__ __launch_bounds__(256) void gemm_split_mma(
    const __nv_bfloat16* __restrict__ Ahi, const __nv_bfloat16* __restrict__ Alo,
    const __nv_bfloat16* __restrict__ Bhi, const __nv_bfloat16* __restrict__ Blo,
    const float* __restrict__ bias, float* __restrict__ Cm,
    int Kt, int ldc, int Nout)
{
    extern __shared__ __align__(16) __nv_bfloat16 sm[];
    const int tid = threadIdx.x;
    const int wid = tid >> 5;
    const int lane = tid & 31;
    const int m0 = blockIdx.y * BMT;
    const int n0 = blockIdx.x * BNT;
    const int wm = (wid & 1) * 64;
    const int wn = (wid >> 1) * 32;
    const int r8 = lane >> 2;
    const int cp = (lane & 3) * 2;

    const __nv_bfloat16* srcs[4] = { Ahi, Alo, Bhi, Blo };
    const int bases[4] = { m0, m0, n0, n0 };

    const int c0 = tid, c1 = tid + 256;
    const int lr0 = c0 >> 2, lc0 = (c0 & 3) * 8;
    const int lr1 = c1 >> 2, lc1 = (c1 & 3) * 8;
    const uint32_t smbase = smem_u32(sm);

    float acc[4][4][4];
#pragma unroll
    for (int i = 0; i < 4; i++)
#pragma unroll
        for (int j = 0; j < 4; j++)
#pragma unroll
            for (int q = 0; q < 4; q++) acc[i][j][q] = 0.f;

    const int NK = Kt >> 5;

#pragma unroll
    for (int t = 0; t < 4; t++) {
        const __nv_bfloat16* sp = srcs[t];
        cpa16(smbase + (uint32_t)((t * 128 + lr0) * APAD + lc0) * 2,
              sp + (size_t)(bases[t] + lr0) * Kt + lc0);
        cpa16(smbase + (uint32_t)((t * 128 + lr1) * APAD + lc1) * 2,
              sp + (size_t)(bases[t] + lr1) * Kt + lc1);
    }
    CP_COMMIT();
    CP_WAIT0();
    __syncthreads();

    for (int kc = 0; kc < NK; kc++) {
        if (kc + 1 < NK) {
            const int sb = ((kc + 1) & 1) * STAGE_ELEMS;
            const int k0 = (kc + 1) << 5;
#pragma unroll
            for (int t = 0; t < 4; t++) {
                const __nv_bfloat16* sp = srcs[t];
                cpa16(smbase + (uint32_t)(sb + (t * 128 + lr0) * APAD + lc0) * 2,
                      sp + (size_t)(bases[t] + lr0) * Kt + k0 + lc0);
                cpa16(smbase + (uint32_t)(sb + (t * 128 + lr1) * APAD + lc1) * 2,
                      sp + (size_t)(bases[t] + lr1) * Kt + k0 + lc1);
            }
            CP_COMMIT();
        }
        const __nv_bfloat16* Ah_ = sm + (kc & 1) * STAGE_ELEMS;
        const __nv_bfloat16* Al_ = Ah_ + TILE_ELEMS;
        const __nv_bfloat16* Bh_ = Ah_ + 2 * TILE_ELEMS;
        const __nv_bfloat16* Bl_ = Ah_ + 3 * TILE_ELEMS;
#pragma unroll
        for (int ks = 0; ks < 2; ks++) {
            const int kb = ks * 16;
            uint32_t afh[4][4], afl[4][4];
#pragma unroll
            for (int im = 0; im < 4; im++) {
                const int rb = wm + im * 16;
                afh[im][0] = *reinterpret_cast<const uint32_t*>(&Ah_[(rb + r8) * APAD + kb + cp]);
                afh[im][1] = *reinterpret_cast<const uint32_t*>(&Ah_[(rb + r8 + 8) * APAD + kb + cp]);
                afh[im][2] = *reinterpret_cast<const uint32_t*>(&Ah_[(rb + r8) * APAD + kb + cp + 8]);
                afh[im][3] = *reinterpret_cast<const uint32_t*>(&Ah_[(rb + r8 + 8) * APAD + kb + cp + 8]);
            }
            uint32_t bfh[4][2], bfl[4][2];
#pragma unroll
            for (int jn = 0; jn < 4; jn++) {
                const int nb = wn + jn * 8;
                bfh[jn][0] = *reinterpret_cast<const uint32_t*>(&Bh_[(nb + r8) * APAD + kb + cp]);
                bfh[jn][1] = *reinterpret_cast<const uint32_t*>(&Bh_[(nb + r8) * APAD + kb + cp + 8]);
                bfl[jn][0] = *reinterpret_cast<const uint32_t*>(&Bl_[(nb + r8) * APAD + kb + cp]);
                bfl[jn][1] = *reinterpret_cast<const uint32_t*>(&Bl_[(nb + r8) * APAD + kb + cp + 8]);
            }
#pragma unroll
            for (int im = 0; im < 4; im++)
#pragma unroll
                for (int jn = 0; jn < 4; jn++) {
                    mma16816(acc[im][jn], afh[im][0], afh[im][1], afh[im][2], afh[im][3], bfh[jn][0], bfh[jn][1]);
                    mma16816(acc[im][jn], afh[im][0], afh[im][1], afh[im][2], afh[im][3], bfl[jn][0], bfl[jn][1]);
                }
#pragma unroll
            for (int im = 0; im < 4; im++) {
                const int rb = wm + im * 16;
                afl[im][0] = *reinterpret_cast<const uint32_t*>(&Al_[(rb + r8) * APAD + kb + cp]);
                afl[im][1] = *reinterpret_cast<const uint32_t*>(&Al_[(rb + r8 + 8) * APAD + kb + cp]);
                afl[im][2] = *reinterpret_cast<const uint32_t*>(&Al_[(rb + r8) * APAD + kb + cp + 8]);
                afl[im][3] = *reinterpret_cast<const uint32_t*>(&Al_[(rb + r8 + 8) * APAD + kb + cp + 8]);
            }
#pragma unroll
            for (int im = 0; im < 4; im++)
#pragma unroll
                for (int jn = 0; jn < 4; jn++)
                    mma16816(acc[im][jn], afl[im][0], afl[im][1], afl[im][2], afl[im][3], bfh[jn][0], bfh[jn][1]);
        }
        if (kc + 1 < NK) {
            CP_WAIT0();
            __syncthreads();
        }
    }

#pragma unroll
    for (int im = 0; im < 4; im++) {
#pragma unroll
        for (int jn = 0; jn < 4; jn++) {
            const int col = n0 + wn + jn * 8 + cp;
            if (col < Nout) {
                const float bx = bias[col], by = bias[col + 1];
                const int row0 = m0 + wm + im * 16 + r8;
                float2 v0 = { acc[im][jn][0] + bx, acc[im][jn][1] + by };
                float2 v1 = { acc[im][jn][2] + bx, acc[im][jn][3] + by };
                *reinterpret_cast<float2*>(&Cm[(size_t)row0 * ldc + col]) = v0;
                *reinterpret_cast<float2*>(&Cm[(size_t)(row0 + 8) * ldc + col]) = v1;
            }
        }
    }
}

// -------------------- prep kernels ------------------------------------------
__global__ __launch_bounds__(256) void wtrans_split(
    const float* __restrict__ W, __nv_bfloat16* __restrict__ hi,
    __nv_bfloat16* __restrict__ lo, int Kd, int N)
{
    int i = blockIdx.x * 256 + threadIdx.x;
    if (i >= N * Kd) return;
    int n = i / Kd, k = i % Kd;
    split2(W[(size_t)k * N + n], hi[i], lo[i]);
}

__global__ __launch_bounds__(256) void wsmall_prep(
    const float* __restrict__ wf, const float* __restrict__ ww,
    const float* __restrict__ bf, const float* __restrict__ bw,
    __nv_bfloat16* __restrict__ hi, __nv_bfloat16* __restrict__ lo,
    float* __restrict__ bc)
{
    int i = blockIdx.x * 256 + threadIdx.x;
    if (i < NSMPAD * CC) {
        int n = i / CC, k = i % CC;
        float v = 0.f;
        if (n < KK) v = wf[k * KK + n];
        else if (n < NSMALL) v = ww[k * NWW + (n - KK)];
        split2(v, hi[i], lo[i]);
    }
    if (i < NSP) {
        float v = 0.f;
        if (i < KK) v = bf[i];
        else if (i < NSMALL) v = bw[i - KK];
        bc[i] = v;
    }
}

// ---------- per-token: channel conv xf + banded softmax (one warp/token) ----
__global__ __launch_bounds__(256) void post_small(
    const float* __restrict__ raw, const float* __restrict__ x,
    const int* __restrict__ mask, float* __restrict__ attn,
    __nv_bfloat16* __restrict__ zhi, __nv_bfloat16* __restrict__ zlo)
{
    __shared__ float xpad[8][CC + 2 * PADK];
    const int warp = threadIdx.x >> 5;
    const int lane = threadIdx.x & 31;
    const int t = blockIdx.x * 8 + warp;
    const int b = t >> 10;
    const int tt = t & 1023;

    float* xp = xpad[warp];
    for (int i = lane; i < CC + 2 * PADK; i += 32) {
        int c = i - PADK;
        xp[i] = (c >= 0 && c < CC) ? x[(size_t)t * CC + c] : 0.f;
    }
    __syncwarp();

    const float mk = (mask[b * TT + tt] != 0) ? 1.f : 0.f;
    float wv = (lane < KK) ? raw[(size_t)t * NSP + lane] : 0.f;
    float acc[8];
#pragma unroll
    for (int q = 0; q < 8; q++) acc[q] = 0.f;
    for (int j = 0; j < KK; j++) {
        float wj = __shfl_sync(0xffffffffu, wv, j);
#pragma unroll
        for (int q = 0; q < 8; q++) acc[q] = fmaf(wj, xp[lane + q * 32 + j], acc[q]);
    }
#pragma unroll
    for (int q = 0; q < 8; q++) {
        float v = acc[q] * mk;
        __nv_bfloat16 h_, l_;
        split2(v, h_, l_);
        size_t o = (size_t)t * C2 + CC + lane + q * 32;
        zhi[o] = h_; zlo[o] = l_;
    }

    const int s = tt + lane - PADK;
    const bool valid = (lane < KK) && (s >= 0) && (s < TT);
#pragma unroll
    for (int h = 0; h < HH; h++) {
        float v = valid ? raw[(size_t)t * NSP + KK + h * KK + lane] : -INFINITY;
        float mx = v;
#pragma unroll
        for (int o = 16; o; o >>= 1) mx = fmaxf(mx, __shfl_xor_sync(0xffffffffu, mx, o));
        float e = valid ? expf(v - mx) : 0.f;
        float sm = e;
#pragma unroll
        for (int o = 16; o; o >>= 1) sm += __shfl_xor_sync(0xffffffffu, sm, o);
        if (lane < KK) attn[(size_t)t * NWW + h * KK + lane] = e / sm;
    }
}

// ---------- banded attention apply ------------------------------------------
#define TCTILE 64
#define TCROWS (TCTILE + 2 * PADK) // 94
__global__ __launch_bounds__(256) void timeconv(
    const float* __restrict__ x, const float* __restrict__ attn,
    const int* __restrict__ mask,
    __nv_bfloat16* __restrict__ zhi, __nv_bfloat16* __restrict__ zlo)
{
    extern __shared__ float smemf[];
    float* xs = smemf;                       // TCROWS * CC
    float* ats = smemf + TCROWS * CC;        // TCTILE * NWW
    __shared__ float msk[TCTILE];

    const int b = blockIdx.x >> 4;
    const int tb = (blockIdx.x & 15) * TCTILE;
    const int tid = threadIdx.x;
    const int c = tid;

    for (int r = 0; r < TCROWS; r++) {
        int s = tb - PADK + r;
        xs[r * CC + c] = (s >= 0 && s < TT)
            ? x[((size_t)b * TT + s) * CC + c] : 0.f;
    }
    for (int i = tid; i < TCTILE * NWW; i += 256)
        ats[i] = attn[((size_t)b * TT + tb) * NWW + i];
    if (tid < TCTILE) msk[tid] = (mask[b * TT + tb + tid] != 0) ? 1.f : 0.f;
    __syncthreads();

    const int h = c >> 6;
    for (int tt = 0; tt < TCTILE; tt++) {
        const float* a = &ats[tt * NWW + h * KK];
        const float* xr = &xs[tt * CC + c];
        float acc = 0.f;
#pragma unroll
        for (int j = 0; j < KK; j++) acc = fmaf(a[j], xr[j * CC], acc);
        float v = acc * msk[tt];
        __nv_bfloat16 h_, l_;
        split2(v, h_, l_);
        size_t o = ((size_t)b * TT + tb + tt) * C2 + c;
        zhi[o] = h_; zlo[o] = l_;
    }
}

// ---------------------------------------------------------------------------
extern "C" void kernel_launch(void* const* d_in, const int* in_sizes, int n_in,
                              void* d_out, int out_size)
{
    const float* query = (const float*)d_in[0];
    const int* mask = (const int*)d_in[3];
    const float* w1 = (const float*)d_in[4];
    const float* b1 = (const float*)d_in[5];
    const float* w2 = (const float*)d_in[6];
    const float* b2 = (const float*)d_in[7];
    const float* ww = (const float*)d_in[8];
    const float* bw = (const float*)d_in[9];
    const float* wf = (const float*)d_in[10];
    const float* bf = (const float*)d_in[11];
    float* out = (float*)d_out;

    void* p;
    cudaGetSymbolAddress(&p, g_x);      float* dx = (float*)p;
    cudaGetSymbolAddress(&p, g_xhi);    __nv_bfloat16* dxhi = (__nv_bfloat16*)p;
    cudaGetSymbolAddress(&p, g_xlo);    __nv_bfloat16* dxlo = (__nv_bfloat16*)p;
    cudaGetSymbolAddress(&p, g_zhi);    __nv_bfloat16* dzhi = (__nv_bfloat16*)p;
    cudaGetSymbolAddress(&p, g_zlo);    __nv_bfloat16* dzlo = (__nv_bfloat16*)p;
    cudaGetSymbolAddress(&p, g_raw);    float* draw = (float*)p;
    cudaGetSymbolAddress(&p, g_attn);   float* dattn = (float*)p;
    cudaGetSymbolAddress(&p, g_w1t_hi); __nv_bfloat16* w1h = (__nv_bfloat16*)p;
    cudaGetSymbolAddress(&p, g_w1t_lo); __nv_bfloat16* w1l = (__nv_bfloat16*)p;
    cudaGetSymbolAddress(&p, g_w2t_hi); __nv_bfloat16* w2h = (__nv_bfloat16*)p;
    cudaGetSymbolAddress(&p, g_w2t_lo); __nv_bfloat16* w2l = (__nv_bfloat16*)p;
    cudaGetSymbolAddress(&p, g_wst_hi); __nv_bfloat16* wsh = (__nv_bfloat16*)p;
    cudaGetSymbolAddress(&p, g_wst_lo); __nv_bfloat16* wsl = (__nv_bfloat16*)p;
    cudaGetSymbolAddress(&p, g_bsmall); float* dbs = (float*)p;

    static bool attr_done = false;
    if (!attr_done) {
        cudaFuncSetAttribute(gemm1_glu,
                             cudaFuncAttributeMaxDynamicSharedMemorySize, G1_SMEM_BYTES);
        cudaFuncSetAttribute(gemm_split_mma,
                             cudaFuncAttributeMaxDynamicSharedMemorySize, GSMEM_BYTES);
        cudaFuncSetAttribute(timeconv, cudaFuncAttributeMaxDynamicSharedMemorySize,
                             (TCROWS * CC + TCTILE * NWW) * (int)sizeof(float));
        attr_done = true;
    }

    // prep: weight splits
    wtrans_split<<<(C2 * CC + 255) / 256, 256>>>(w1, w1h, w1l, CC, C2);
    wtrans_split<<<(CC * C2 + 255) / 256, 256>>>(w2, w2h, w2l, C2, CC);
    wsmall_prep<<<(NSMPAD * CC + 255) / 256, 256>>>(wf, ww, bf, bw, wsh, wsl, dbs);

    // 1) x = GLU(query @ w1 + b1), fused (writes x fp32 + xhi/xlo bf16)
    gemm1_glu<<<dim3(2, BT / BMT), 256, G1_SMEM_BYTES>>>(
        query, w1h, w1l, b1, dx, dxhi, dxlo);
    // 2) raw = x @ [wf|ww] + [bf|bw]  (16384x160, K=256; 2 N-blocks of 128)
    gemm_split_mma<<<dim3(NSMPAD / BNT, BT / BMT), 256, GSMEM_BYTES>>>(
        dxhi, dxlo, wsh, wsl, dbs, draw, CC, NSP, NSP);
    // 3) channel conv xf (-> z[:,256:512]) + banded softmax (-> attn)
    post_small<<<BT / 8, 256>>>(draw, dx, mask, dattn, dzhi, dzlo);
    // 4) banded attention apply (-> z[:,0:256])
    timeconv<<<BB * (TT / TCTILE), 256,
               (TCROWS * CC + TCTILE * NWW) * sizeof(float)>>>(dx, dattn, mask, dzhi, dzlo);
    // 5) out = z @ w2 + b2   (16384x256, K=512)
    gemm_split_mma<<<dim3(CC / BNT, BT / BMT), 256, GSMEM_BYTES>>>(
        dzhi, dzlo, w2h, w2l, b2, out, C2, CC, CC);
}